// round 10
// baseline (speedup 1.0000x reference)
#include <cuda_runtime.h>
#include <math.h>
#include <string.h>

#define HDIM   256
#define NCELL  32
#define DTH    31
#define EPSF   1e-7f
#define TINYF  1e-10f
#define GTAB   1024                  // table cells; nodes = GTAB+1
#define KCH    32                    // k-chunks for u,c partial reduction
#define TROWS  16                    // table rows per fused block

// ---------------- device scratch (no cudaMalloc allowed) ----------------
__device__ float g_Bmat[DTH * 64];          // host-computed basis, [d][j]
__device__ float g_upart[KCH * HDIM];       // partial sums of u
__device__ float g_cpart[KCH * HDIM];       // partial sums of c (pre-b1)
__device__ float g_Atab[(GTAB + 64) * 64];  // A table rows (+pad)

// ============================================================================
// Host: numpy SVD null-space basis B = Vt[33:].T via Householder LQ
// (dgesdd Path 4t: dgelqf + dorglq — rows 33..63 of the LQ Q-factor are
// exactly Vt[33:]). Depends only on NC=32, no runtime inputs -> host fp64.
// ============================================================================
static void compute_basis_host(float* Bout /* [DTH][64] */)
{
    static double L[33][64];
    static double Bm[DTH][64];
    static double tau[33];
    memset(L, 0, sizeof(L));
    memset(Bm, 0, sizeof(Bm));

    for (int i = 1; i < NCELL; i++) {
        double xi = (double)i / (double)NCELL;
        L[i - 1][2 * (i - 1)]     = xi;
        L[i - 1][2 * (i - 1) + 1] = 1.0;
        L[i - 1][2 * i]           = -xi;
        L[i - 1][2 * i + 1]       = -1.0;
    }
    L[NCELL - 1][1]               = 1.0;
    L[NCELL][2 * (NCELL - 1)]     = 1.0;
    L[NCELL][2 * (NCELL - 1) + 1] = 1.0;

    for (int i = 0; i < 33; i++) {
        double xn2 = 0.0;
        for (int j = i + 1; j < 64; j++) xn2 += L[i][j] * L[i][j];
        if (xn2 == 0.0) { tau[i] = 0.0; continue; }
        double alpha = L[i][i];
        double beta = sqrt(alpha * alpha + xn2);
        beta = (alpha >= 0.0) ? -beta : beta;
        tau[i] = (beta - alpha) / beta;
        double sc = 1.0 / (alpha - beta);
        for (int j = i + 1; j < 64; j++) L[i][j] *= sc;
        L[i][i] = beta;
        for (int r = i + 1; r < 33; r++) {
            double w = L[r][i];
            for (int j = i + 1; j < 64; j++) w += L[r][j] * L[i][j];
            w *= tau[i];
            L[r][i] -= w;
            for (int j = i + 1; j < 64; j++) L[r][j] -= w * L[i][j];
        }
    }
    for (int r = 0; r < DTH; r++) Bm[r][33 + r] = 1.0;
    for (int i = 32; i >= 0; i--) {
        if (tau[i] == 0.0) continue;
        for (int r = 0; r < DTH; r++) {
            double w = Bm[r][i];
            for (int j = i + 1; j < 64; j++) w += Bm[r][j] * L[i][j];
            w *= tau[i];
            Bm[r][i] -= w;
            for (int j = i + 1; j < 64; j++) Bm[r][j] -= w * L[i][j];
        }
    }
    for (int d = 0; d < DTH; d++)
        for (int j = 0; j < 64; j++)
            Bout[d * 64 + j] = (float)Bm[d][j];
}

// ============================================================================
// k0u: stage-1 partial reduction of u = w0@w1, c = b0@w1.
// ============================================================================
__global__ void __launch_bounds__(256) k0u_part(
    const float* __restrict__ w0, const float* __restrict__ b0,
    const float* __restrict__ w1)
{
    const int tid = threadIdx.x;
    const int b = blockIdx.x;
    float uu = 0.f, cc = 0.f;
#pragma unroll
    for (int kk = 0; kk < HDIM / KCH; kk++) {
        int k = b * (HDIM / KCH) + kk;
        float wv = w1[k * HDIM + tid];
        uu = fmaf(w0[k], wv, uu);
        cc = fmaf(b0[k], wv, cc);
    }
    g_upart[b * HDIM + tid] = uu;
    g_cpart[b * HDIM + tid] = cc;
}

// ============================================================================
// kT_fused: per block, TROWS=16 table rows, FULL pipeline to A:
//   h1 = relu(x*u+c);  H2 = relu(h1@w2+b2)  (16x256 GEMM, regs);
//   T  = H2@w3 + b3    (16x31);
//   A  = T@B^T         -> g_Atab rows.
// 65 blocks x 256 threads; no global H2 round-trip, one launch fewer.
// ============================================================================
__global__ void __launch_bounds__(256) kT_fused(
    const float* __restrict__ b1,
    const float* __restrict__ w2, const float* __restrict__ b2,
    const float* __restrict__ w3, const float* __restrict__ b3, int nrows)
{
    __shared__ float us[HDIM], cs[HDIM];
    __shared__ float xs[TROWS];
    __shared__ float As[8][20];            // h1 chunk [kk][i]
    __shared__ float Bbuf[8 * 256];        // GEMM B-tiles, then basis (1984 fl)
    __shared__ float H2s[TROWS][257];      // [i][k]
    __shared__ float Ts[32][17];           // [d][i]

    const int i0 = blockIdx.x * TROWS;
    const int tid = threadIdx.x;

    // u,c from partials (fixed order -> deterministic)
    {
        float uu = 0.f, cc = 0.f;
#pragma unroll
        for (int b = 0; b < KCH; b++) {
            uu += g_upart[b * HDIM + tid];
            cc += g_cpart[b * HDIM + tid];
        }
        us[tid] = uu;
        cs[tid] = cc + b1[tid];
    }
    if (tid < TROWS)
        xs[tid] = (float)(i0 + tid) * (1.0f / (float)GTAB);
    __syncthreads();

    // ---- stage 2: H2 = relu(h1 @ w2 + b2), 16x256 tile, BK=8 ----
    const int tx = tid & 31;       // 32 col groups of 8
    const int ty = tid >> 5;       // 8 row groups of 2

    float acc[2][8];
#pragma unroll
    for (int m = 0; m < 2; m++)
#pragma unroll
        for (int nn = 0; nn < 8; nn++) acc[m][nn] = 0.f;

    for (int kc = 0; kc < HDIM; kc += 8) {
        if (tid < 128) {
            int kk = tid >> 4, ii = tid & 15;
            As[kk][ii] = fmaxf(fmaf(xs[ii], us[kc + kk], cs[kc + kk]), 0.f);
        }
#pragma unroll
        for (int s = 0; s < 8; s++) {
            int e = tid + s * 256;
            int kk = e >> 8, jj = e & 255;
            Bbuf[kk * 256 + jj] = w2[(kc + kk) * HDIM + jj];
        }
        __syncthreads();
#pragma unroll
        for (int kk = 0; kk < 8; kk++) {
            float a0 = As[kk][ty * 2];
            float a1 = As[kk][ty * 2 + 1];
            float4 b0v = *reinterpret_cast<const float4*>(&Bbuf[kk * 256 + tx * 8]);
            float4 b1v = *reinterpret_cast<const float4*>(&Bbuf[kk * 256 + tx * 8 + 4]);
            float b[8] = {b0v.x, b0v.y, b0v.z, b0v.w, b1v.x, b1v.y, b1v.z, b1v.w};
#pragma unroll
            for (int nn = 0; nn < 8; nn++) {
                acc[0][nn] = fmaf(a0, b[nn], acc[0][nn]);
                acc[1][nn] = fmaf(a1, b[nn], acc[1][nn]);
            }
        }
        __syncthreads();
    }

    // write H2 into smem [i][k]
#pragma unroll
    for (int nn = 0; nn < 8; nn++) {
        float bb = b2[tx * 8 + nn];
        H2s[ty * 2 + 0][tx * 8 + nn] = fmaxf(acc[0][nn] + bb, 0.f);
        H2s[ty * 2 + 1][tx * 8 + nn] = fmaxf(acc[1][nn] + bb, 0.f);
    }
    __syncthreads();

    // reuse Bbuf for the basis
    if (tid < DTH * 64 - 1792) Bbuf[1792 + tid] = g_Bmat[1792 + tid];
#pragma unroll
    for (int s = 0; s < 7; s++)
        Bbuf[tid + s * 256] = g_Bmat[tid + s * 256];

    // ---- stage 3: T = H2 @ w3 + b3 ----
    {
        const int i = tid & 15;
        const int dg = tid >> 4;         // 16 groups x 2 d
        const int d0 = dg * 2, d1 = d0 + 1;
        float a0 = 0.f, a1 = 0.f;
#pragma unroll 4
        for (int k = 0; k < HDIM; k++) {
            float h = H2s[i][k];
            a0 = fmaf(h, __ldg(&w3[k * DTH + d0]), a0);
            if (d1 < DTH) a1 = fmaf(h, __ldg(&w3[k * DTH + d1]), a1);
        }
        Ts[d0][i] = a0 + b3[d0];
        if (d1 < DTH) Ts[d1][i] = a1 + b3[d1];
    }
    __syncthreads();

    // ---- stage 4: A = T @ B^T -> g_Atab ----
    {
        const int j = tid & 63;
        const int ig = tid >> 6;         // 4 groups x 4 rows
        float a4[4] = {0.f, 0.f, 0.f, 0.f};
#pragma unroll
        for (int d = 0; d < DTH; d++) {
            float bv = Bbuf[d * 64 + j];
#pragma unroll
            for (int m = 0; m < 4; m++)
                a4[m] = fmaf(Ts[d][ig + m * 4], bv, a4[m]);
        }
#pragma unroll
        for (int m = 0; m < 4; m++) {
            int row = i0 + ig + m * 4;
            if (row < nrows)
                g_Atab[row * 64 + j] = a4[m];
        }
    }
}

// ============================================================================
// k3: CPAB integration, 1 point/thread (reverted: 2-pt pairing was neutral
//     and raised regs). On-demand per-cell lerp from L2-resident table;
//     exact fixpoint early-exit; fast intrinsics except precise '/' for e=b/a.
// ============================================================================
__global__ void __launch_bounds__(256) k3_integrate(const float* __restrict__ x,
                                                    float* __restrict__ out, int n)
{
    const int ip = blockIdx.x * 256 + threadIdx.x;
    if (ip >= n) return;

    float x1 = x[2 * ip + 1];
    x1 = fminf(fmaxf(x1, EPSF), 1.0f - EPSF);
    float f = x1 * (float)GTAB;
    int r = (int)f;
    r = max(0, min(r, GTAB - 1));
    float fr = f - (float)r;
    const float2* row0 = reinterpret_cast<const float2*>(&g_Atab[r * 64]);
    const float2* row1 = reinterpret_cast<const float2*>(&g_Atab[(r + 1) * 64]);

    float x2 = x[2 * ip];
    float xc = fminf(fmaxf(x2, EPSF), 1.0f - EPSF);
    float t = 1.0f;
    float S = 0.0f;
    const float inv = 1.0f / (float)NCELL;
    const float INF = __int_as_float(0x7f800000);

#pragma unroll 1
    for (int it = 0; it < NCELL + 2; it++) {
        int c = (int)(xc * (float)NCELL);
        c = max(0, min(c, NCELL - 1));
        float2 p0 = __ldg(&row0[c]);
        float2 p1 = __ldg(&row1[c]);
        float a = fmaf(fr, p1.x - p0.x, p0.x);
        float b = fmaf(fr, p1.y - p0.y, p0.y);
        float v = a * xc + b;
        float xbnd = ((v >= 0.f) ? (float)(c + 1) : (float)c) * inv;
        bool  small_a = fabsf(a) < TINYF;
        float safe_a = small_a ? 1.0f : a;
        float e = b / safe_a;                       // precise: drives drift matching
        float denom = xc + e;
        float safe_denom = (fabsf(denom) < TINYF) ? ((denom >= 0.f) ? TINYF : -TINYF) : denom;
        float ratio = __fdividef(xbnd + e, safe_denom);
        float thit_exp = __fdividef(__logf(fmaxf(ratio, TINYF)), safe_a);
        float safe_b = (fabsf(b) < TINYF) ? TINYF : b;
        float thit_lin = __fdividef(xbnd - xc, safe_b);
        float thit = small_a ? thit_lin : ((ratio > TINYF) ? thit_exp : INF);
        thit = (thit <= 0.f) ? INF : thit;
        float dt = fminf(thit, t);
        bool cross = (thit <= t);
        float x_exp = (xc + e) * __expf(a * dt) - e;
        float x_lin = xc + b * dt;
        float xn = small_a ? x_lin : x_exp;
        float nudge = (v >= 0.f) ? 1e-7f : -1e-7f;
        xn = cross ? (xbnd + nudge) : xn;
        xn = fminf(fmaxf(xn, EPSF), 1.0f - EPSF);
        S += a * dt;
        t = t - dt;
        bool done = (dt == 0.0f) && (xn == xc);     // exact fixpoint
        xc = xn;
        if (__all_sync(0xffffffffu, done)) break;
    }

    out[2 * ip]     = xc;
    out[2 * ip + 1] = x1;
    out[2 * n + 2 * ip]     = S;
    out[2 * n + 2 * ip + 1] = 0.0f;
}

// ============================================================================
static float s_Bhost[DTH * 64];   // persists across graph replays

extern "C" void kernel_launch(void* const* d_in, const int* in_sizes, int n_in,
                              void* d_out, int out_size)
{
    const float* x  = (const float*)d_in[0];
    const float* w0 = (const float*)d_in[1];
    const float* b0 = (const float*)d_in[2];
    const float* w1 = (const float*)d_in[3];
    const float* b1 = (const float*)d_in[4];
    const float* w2 = (const float*)d_in[5];
    const float* b2 = (const float*)d_in[6];
    const float* w3 = (const float*)d_in[7];
    const float* b3 = (const float*)d_in[8];
    float* out = (float*)d_out;

    int n = in_sizes[0] / 2;
    const int nrows = GTAB + 1;

    compute_basis_host(s_Bhost);    // input-independent, deterministic
    cudaMemcpyToSymbolAsync(g_Bmat, s_Bhost, sizeof(s_Bhost), 0,
                            cudaMemcpyHostToDevice, 0);

    k0u_part<<<KCH, 256>>>(w0, b0, w1);

    kT_fused<<<(nrows + TROWS - 1) / TROWS, 256>>>(b1, w2, b2, w3, b3, nrows);

    k3_integrate<<<(n + 255) / 256, 256>>>(x, out, n);
}

// round 11
// speedup vs baseline: 1.1132x; 1.1132x over previous
#include <cuda_runtime.h>
#include <math.h>
#include <string.h>

#define HDIM   256
#define NCELL  32
#define DTH    31
#define EPSF   1e-7f
#define TINYF  1e-10f
#define GTAB   1024                  // table cells; nodes = GTAB+1
#define KCH    64                    // k-chunks for u,c partial reduction

// ---------------- device scratch (no cudaMalloc allowed) ----------------
__device__ float g_Bmat[DTH * 64];          // host-computed basis, [d][j]
__device__ float g_upart[KCH * HDIM];       // partial sums of u
__device__ float g_cpart[KCH * HDIM];       // partial sums of c (pre-b1)
__device__ float g_H2[(GTAB + 64) * HDIM];  // h2 table (+pad rows)
__device__ float g_Atab[(GTAB + 2) * 64];   // A table rows

// ============================================================================
// Host: numpy SVD null-space basis B = Vt[33:].T via Householder LQ
// (dgesdd Path 4t: dgelqf + dorglq — rows 33..63 of the LQ Q-factor are
// exactly Vt[33:]). Depends only on NC=32, no runtime inputs -> host fp64.
// ============================================================================
static void compute_basis_host(float* Bout /* [DTH][64] */)
{
    static double L[33][64];
    static double Bm[DTH][64];
    static double tau[33];
    memset(L, 0, sizeof(L));
    memset(Bm, 0, sizeof(Bm));

    for (int i = 1; i < NCELL; i++) {
        double xi = (double)i / (double)NCELL;
        L[i - 1][2 * (i - 1)]     = xi;
        L[i - 1][2 * (i - 1) + 1] = 1.0;
        L[i - 1][2 * i]           = -xi;
        L[i - 1][2 * i + 1]       = -1.0;
    }
    L[NCELL - 1][1]               = 1.0;
    L[NCELL][2 * (NCELL - 1)]     = 1.0;
    L[NCELL][2 * (NCELL - 1) + 1] = 1.0;

    for (int i = 0; i < 33; i++) {
        double xn2 = 0.0;
        for (int j = i + 1; j < 64; j++) xn2 += L[i][j] * L[i][j];
        if (xn2 == 0.0) { tau[i] = 0.0; continue; }
        double alpha = L[i][i];
        double beta = sqrt(alpha * alpha + xn2);
        beta = (alpha >= 0.0) ? -beta : beta;
        tau[i] = (beta - alpha) / beta;
        double sc = 1.0 / (alpha - beta);
        for (int j = i + 1; j < 64; j++) L[i][j] *= sc;
        L[i][i] = beta;
        for (int r = i + 1; r < 33; r++) {
            double w = L[r][i];
            for (int j = i + 1; j < 64; j++) w += L[r][j] * L[i][j];
            w *= tau[i];
            L[r][i] -= w;
            for (int j = i + 1; j < 64; j++) L[r][j] -= w * L[i][j];
        }
    }
    for (int r = 0; r < DTH; r++) Bm[r][33 + r] = 1.0;
    for (int i = 32; i >= 0; i--) {
        if (tau[i] == 0.0) continue;
        for (int r = 0; r < DTH; r++) {
            double w = Bm[r][i];
            for (int j = i + 1; j < 64; j++) w += Bm[r][j] * L[i][j];
            w *= tau[i];
            Bm[r][i] -= w;
            for (int j = i + 1; j < 64; j++) Bm[r][j] -= w * L[i][j];
        }
    }
    for (int d = 0; d < DTH; d++)
        for (int j = 0; j < 64; j++)
            Bout[d * 64 + j] = (float)Bm[d][j];
}

// ============================================================================
// k0u: stage-1 partial reduction of u = w0@w1, c = b0@w1.
//      64 blocks x 256 threads; block b covers k in [4b, 4b+4).
// ============================================================================
__global__ void __launch_bounds__(256) k0u_part(
    const float* __restrict__ w0, const float* __restrict__ b0,
    const float* __restrict__ w1)
{
    const int tid = threadIdx.x;
    const int b = blockIdx.x;
    float uu = 0.f, cc = 0.f;
#pragma unroll
    for (int kk = 0; kk < HDIM / KCH; kk++) {
        int k = b * (HDIM / KCH) + kk;
        float wv = w1[k * HDIM + tid];
        uu = fmaf(w0[k], wv, uu);
        cc = fmaf(b0[k], wv, cc);
    }
    g_upart[b * HDIM + tid] = uu;
    g_cpart[b * HDIM + tid] = cc;
}

// ============================================================================
// kT1: h2 table.  H2[g] = relu( relu(x_g*u + c) @ w2 + b2 ), x_g = g/GTAB.
//      Per-block u,c from partials (fixed order -> deterministic).
//      32x64 tile, BK=16, 256 threads, 4x2 microtile.
// ============================================================================
__global__ void __launch_bounds__(256) kT1_h2tab(
    const float* __restrict__ b1,
    const float* __restrict__ w2, const float* __restrict__ b2, int nrows)
{
    __shared__ float us[HDIM], cs[HDIM];
    __shared__ float xs[32];
    __shared__ float As[16][36];   // stride 144B (16B-aligned)
    __shared__ float Bs[16][64];

    const int i0 = blockIdx.x * 32;
    const int j0 = blockIdx.y * 64;
    const int tid = threadIdx.x;

    {
        float uu = 0.f, cc = 0.f;
#pragma unroll
        for (int b = 0; b < KCH; b++) {
            uu += g_upart[b * HDIM + tid];
            cc += g_cpart[b * HDIM + tid];
        }
        us[tid] = uu;
        cs[tid] = cc + b1[tid];
    }
    if (tid < 32)
        xs[tid] = (float)(i0 + tid) * (1.0f / (float)GTAB);
    __syncthreads();

    const int tx = tid & 31;       // 32 col groups of 2
    const int ty = tid >> 5;       // 8 row groups of 4

    float acc[4][2];
#pragma unroll
    for (int m = 0; m < 4; m++) { acc[m][0] = 0.f; acc[m][1] = 0.f; }

    for (int k0 = 0; k0 < HDIM; k0 += 16) {
#pragma unroll
        for (int s = 0; s < 2; s++) {           // As: 512 elems
            int e = tid + s * 256;
            int kk = e >> 5, ii = e & 31;
            As[kk][ii] = fmaxf(fmaf(xs[ii], us[k0 + kk], cs[k0 + kk]), 0.f);
        }
#pragma unroll
        for (int s = 0; s < 4; s++) {           // Bs: 1024 elems
            int e = tid + s * 256;
            int kk = e >> 6, jj = e & 63;
            Bs[kk][jj] = w2[(k0 + kk) * HDIM + j0 + jj];
        }
        __syncthreads();
#pragma unroll
        for (int kk = 0; kk < 16; kk++) {
            float4 a4 = *reinterpret_cast<const float4*>(&As[kk][ty * 4]);
            float2 bv = *reinterpret_cast<const float2*>(&Bs[kk][tx * 2]);
            float a[4] = {a4.x, a4.y, a4.z, a4.w};
#pragma unroll
            for (int m = 0; m < 4; m++) {
                acc[m][0] = fmaf(a[m], bv.x, acc[m][0]);
                acc[m][1] = fmaf(a[m], bv.y, acc[m][1]);
            }
        }
        __syncthreads();
    }

    float bb0 = b2[j0 + tx * 2];
    float bb1 = b2[j0 + tx * 2 + 1];
#pragma unroll
    for (int m = 0; m < 4; m++) {
        int row = i0 + ty * 4 + m;
        if (row < nrows) {
            float2 v;
            v.x = fmaxf(acc[m][0] + bb0, 0.f);
            v.y = fmaxf(acc[m][1] + bb1, 0.f);
            *reinterpret_cast<float2*>(&g_H2[row * HDIM + j0 + tx * 2]) = v;
        }
    }
}

// ============================================================================
// kT2: A table directly:  A = (H2 @ w3 + b3) @ B^T.
// ============================================================================
__global__ void __launch_bounds__(256) kT2_atab(
    const float* __restrict__ w3, const float* __restrict__ b3, int nrows)
{
    __shared__ float H2s[256][33];   // [k][i], 33.8 KB
    __shared__ float Ts[32][33];     // [d][i] (+b3 folded)
    __shared__ float Bs[DTH][64];    // basis

    const int i0 = blockIdx.x * 32;
    const int tid = threadIdx.x;

#pragma unroll
    for (int s = 0; s < 8; s++) {
        int e = tid + s * 256;           // 0..2047 float4 units
        int i = e >> 6, kq = e & 63;
        float4 v = *reinterpret_cast<const float4*>(&g_H2[(i0 + i) * HDIM + kq * 4]);
        H2s[kq * 4 + 0][i] = v.x;
        H2s[kq * 4 + 1][i] = v.y;
        H2s[kq * 4 + 2][i] = v.z;
        H2s[kq * 4 + 3][i] = v.w;
    }
    for (int e = tid; e < DTH * 64; e += 256)
        Bs[e >> 6][e & 63] = g_Bmat[e];
    __syncthreads();

    // T = H2 @ w3  (+ b3)
    {
        const int i = tid & 31;
        const int dbase = (tid >> 5) * 4;    // 0,4,...,28
        float acc[4] = {0.f, 0.f, 0.f, 0.f};
#pragma unroll 4
        for (int k = 0; k < HDIM; k++) {
            float h = H2s[k][i];
#pragma unroll
            for (int q = 0; q < 4; q++) {
                int d = dbase + q;
                if (d < DTH)
                    acc[q] = fmaf(h, __ldg(&w3[k * DTH + d]), acc[q]);
            }
        }
#pragma unroll
        for (int q = 0; q < 4; q++) {
            int d = dbase + q;
            if (d < DTH) Ts[d][i] = acc[q] + b3[d];
        }
    }
    __syncthreads();

    // A = T @ B^T
    {
        const int j = tid & 63;
        const int ig = tid >> 6;             // 0..3
        float acc8[8];
#pragma unroll
        for (int m = 0; m < 8; m++) acc8[m] = 0.f;
#pragma unroll
        for (int d = 0; d < DTH; d++) {
            float bv = Bs[d][j];
#pragma unroll
            for (int m = 0; m < 8; m++)
                acc8[m] = fmaf(Ts[d][ig + m * 4], bv, acc8[m]);
        }
#pragma unroll
        for (int m = 0; m < 8; m++) {
            int row = i0 + ig + m * 4;
            if (row < nrows)
                g_Atab[row * 64 + j] = acc8[m];
        }
    }
}

// ============================================================================
// k3: CPAB integration, 1 point/thread, next-cell prefetch.
//     The CPAB flow is monotone -> the next visited cell is c + sign(v).
//     Carry (cp, q0, q1): on hit, the iteration's serial chain has no
//     dependent L2 load; predicted-cell loads overlap the MUFU math.
//     Exact fixpoint early-exit; precise '/' for e=b/a.
// ============================================================================
__global__ void __launch_bounds__(256) k3_integrate(const float* __restrict__ x,
                                                    float* __restrict__ out, int n)
{
    const int ip = blockIdx.x * 256 + threadIdx.x;
    if (ip >= n) return;

    float x1 = x[2 * ip + 1];
    x1 = fminf(fmaxf(x1, EPSF), 1.0f - EPSF);
    float f = x1 * (float)GTAB;
    int r = (int)f;
    r = max(0, min(r, GTAB - 1));
    float fr = f - (float)r;
    const float2* row0 = reinterpret_cast<const float2*>(&g_Atab[r * 64]);
    const float2* row1 = reinterpret_cast<const float2*>(&g_Atab[(r + 1) * 64]);

    float x2 = x[2 * ip];
    float xc = fminf(fmaxf(x2, EPSF), 1.0f - EPSF);
    float t = 1.0f;
    float S = 0.0f;
    const float inv = 1.0f / (float)NCELL;
    const float INF = __int_as_float(0x7f800000);

    int cp = -1;                     // predicted cell (invalid first iter)
    float2 q0, q1;

#pragma unroll 1
    for (int it = 0; it < NCELL + 2; it++) {
        int c = (int)(xc * (float)NCELL);
        c = max(0, min(c, NCELL - 1));
        float2 p0, p1;
        if (c == cp) { p0 = q0; p1 = q1; }
        else         { p0 = __ldg(&row0[c]); p1 = __ldg(&row1[c]); }
        float a = fmaf(fr, p1.x - p0.x, p0.x);
        float b = fmaf(fr, p1.y - p0.y, p0.y);
        float v = a * xc + b;
        // prefetch predicted next cell (monotone flow); overlaps math below
        cp = max(0, min(c + ((v >= 0.f) ? 1 : -1), NCELL - 1));
        q0 = __ldg(&row0[cp]);
        q1 = __ldg(&row1[cp]);

        float xbnd = ((v >= 0.f) ? (float)(c + 1) : (float)c) * inv;
        bool  small_a = fabsf(a) < TINYF;
        float safe_a = small_a ? 1.0f : a;
        float e = b / safe_a;                       // precise: drives drift matching
        float denom = xc + e;
        float safe_denom = (fabsf(denom) < TINYF) ? ((denom >= 0.f) ? TINYF : -TINYF) : denom;
        float ratio = __fdividef(xbnd + e, safe_denom);
        float thit_exp = __fdividef(__logf(fmaxf(ratio, TINYF)), safe_a);
        float safe_b = (fabsf(b) < TINYF) ? TINYF : b;
        float thit_lin = __fdividef(xbnd - xc, safe_b);
        float thit = small_a ? thit_lin : ((ratio > TINYF) ? thit_exp : INF);
        thit = (thit <= 0.f) ? INF : thit;
        float dt = fminf(thit, t);
        bool cross = (thit <= t);
        float x_exp = (xc + e) * __expf(a * dt) - e;
        float x_lin = xc + b * dt;
        float xn = small_a ? x_lin : x_exp;
        float nudge = (v >= 0.f) ? 1e-7f : -1e-7f;
        xn = cross ? (xbnd + nudge) : xn;
        xn = fminf(fmaxf(xn, EPSF), 1.0f - EPSF);
        S += a * dt;
        t = t - dt;
        bool done = (dt == 0.0f) && (xn == xc);     // exact fixpoint
        xc = xn;
        if (__all_sync(0xffffffffu, done)) break;
    }

    float2 z; z.x = xc; z.y = x1;
    *reinterpret_cast<float2*>(&out[2 * ip]) = z;
    float2 g; g.x = S; g.y = 0.0f;
    *reinterpret_cast<float2*>(&out[2 * n + 2 * ip]) = g;
}

// ============================================================================
static float s_Bhost[DTH * 64];   // persists across graph replays

extern "C" void kernel_launch(void* const* d_in, const int* in_sizes, int n_in,
                              void* d_out, int out_size)
{
    const float* x  = (const float*)d_in[0];
    const float* w0 = (const float*)d_in[1];
    const float* b0 = (const float*)d_in[2];
    const float* w1 = (const float*)d_in[3];
    const float* b1 = (const float*)d_in[4];
    const float* w2 = (const float*)d_in[5];
    const float* b2 = (const float*)d_in[6];
    const float* w3 = (const float*)d_in[7];
    const float* b3 = (const float*)d_in[8];
    float* out = (float*)d_out;

    int n = in_sizes[0] / 2;
    const int nrows = GTAB + 1;

    compute_basis_host(s_Bhost);    // input-independent, deterministic
    cudaMemcpyToSymbolAsync(g_Bmat, s_Bhost, sizeof(s_Bhost), 0,
                            cudaMemcpyHostToDevice, 0);

    k0u_part<<<KCH, 256>>>(w0, b0, w1);

    dim3 g1((nrows + 31) / 32, 4);
    kT1_h2tab<<<g1, 256>>>(b1, w2, b2, nrows);

    kT2_atab<<<(nrows + 31) / 32, 256>>>(w3, b3, nrows);

    k3_integrate<<<(n + 255) / 256, 256>>>(x, out, n);
}

// round 12
// speedup vs baseline: 1.3129x; 1.1794x over previous
#include <cuda_runtime.h>
#include <math.h>
#include <string.h>

#define HDIM   256
#define NCELL  32
#define DTH    31
#define EPSF   1e-7f
#define TINYF  1e-10f
#define GTAB   1024                  // table cells; nodes = GTAB+1
#define KCH    32                    // k-chunks for u,c partial reduction

// ---------------- device scratch (no cudaMalloc allowed) ----------------
__device__ float g_upart[KCH * HDIM];       // partial sums of u
__device__ float g_cpart[KCH * HDIM];       // partial sums of c (pre-b1)
__device__ float g_H2[(GTAB + 64) * HDIM];  // h2 table (+pad rows)
__device__ float g_Atab[(GTAB + 2) * 64];   // A table rows

struct BParam { float B[DTH * 64]; };       // 7936 B kernel param (sm_90+: 32KB ok)

// ============================================================================
// Host: numpy SVD null-space basis B = Vt[33:].T via Householder LQ
// (dgesdd Path 4t: dgelqf + dorglq — rows 33..63 of the LQ Q-factor are
// exactly Vt[33:]). Depends only on NC=32, no runtime inputs -> host fp64.
// ============================================================================
static void compute_basis_host(float* Bout /* [DTH][64] */)
{
    static double L[33][64];
    static double Bm[DTH][64];
    static double tau[33];
    memset(L, 0, sizeof(L));
    memset(Bm, 0, sizeof(Bm));

    for (int i = 1; i < NCELL; i++) {
        double xi = (double)i / (double)NCELL;
        L[i - 1][2 * (i - 1)]     = xi;
        L[i - 1][2 * (i - 1) + 1] = 1.0;
        L[i - 1][2 * i]           = -xi;
        L[i - 1][2 * i + 1]       = -1.0;
    }
    L[NCELL - 1][1]               = 1.0;
    L[NCELL][2 * (NCELL - 1)]     = 1.0;
    L[NCELL][2 * (NCELL - 1) + 1] = 1.0;

    for (int i = 0; i < 33; i++) {
        double xn2 = 0.0;
        for (int j = i + 1; j < 64; j++) xn2 += L[i][j] * L[i][j];
        if (xn2 == 0.0) { tau[i] = 0.0; continue; }
        double alpha = L[i][i];
        double beta = sqrt(alpha * alpha + xn2);
        beta = (alpha >= 0.0) ? -beta : beta;
        tau[i] = (beta - alpha) / beta;
        double sc = 1.0 / (alpha - beta);
        for (int j = i + 1; j < 64; j++) L[i][j] *= sc;
        L[i][i] = beta;
        for (int r = i + 1; r < 33; r++) {
            double w = L[r][i];
            for (int j = i + 1; j < 64; j++) w += L[r][j] * L[i][j];
            w *= tau[i];
            L[r][i] -= w;
            for (int j = i + 1; j < 64; j++) L[r][j] -= w * L[i][j];
        }
    }
    for (int r = 0; r < DTH; r++) Bm[r][33 + r] = 1.0;
    for (int i = 32; i >= 0; i--) {
        if (tau[i] == 0.0) continue;
        for (int r = 0; r < DTH; r++) {
            double w = Bm[r][i];
            for (int j = i + 1; j < 64; j++) w += Bm[r][j] * L[i][j];
            w *= tau[i];
            Bm[r][i] -= w;
            for (int j = i + 1; j < 64; j++) Bm[r][j] -= w * L[i][j];
        }
    }
    for (int d = 0; d < DTH; d++)
        for (int j = 0; j < 64; j++)
            Bout[d * 64 + j] = (float)Bm[d][j];
}

// ============================================================================
// k0u: stage-1 partial reduction of u = w0@w1, c = b0@w1.
//      grid (KCH, 2) x 128 threads: block (b,h) covers k in [8b,8b+8),
//      j in [128h, 128h+128).  64 blocks -> better SM coverage than 32.
// ============================================================================
__global__ void __launch_bounds__(128) k0u_part(
    const float* __restrict__ w0, const float* __restrict__ b0,
    const float* __restrict__ w1)
{
    const int j = blockIdx.y * 128 + threadIdx.x;
    const int b = blockIdx.x;
    float uu = 0.f, cc = 0.f;
#pragma unroll
    for (int kk = 0; kk < HDIM / KCH; kk++) {
        int k = b * (HDIM / KCH) + kk;
        float wv = w1[k * HDIM + j];
        uu = fmaf(w0[k], wv, uu);
        cc = fmaf(b0[k], wv, cc);
    }
    g_upart[b * HDIM + j] = uu;
    g_cpart[b * HDIM + j] = cc;
}

// ============================================================================
// kT1: h2 table.  H2[g] = relu( relu(x_g*u + c) @ w2 + b2 ), x_g = g/GTAB.
//      Per-block u,c from partials (fixed order -> deterministic).
//      32x64 tile, BK=16, 256 threads, 4x2 microtile.
// ============================================================================
__global__ void __launch_bounds__(256) kT1_h2tab(
    const float* __restrict__ b1,
    const float* __restrict__ w2, const float* __restrict__ b2, int nrows)
{
    __shared__ float us[HDIM], cs[HDIM];
    __shared__ float xs[32];
    __shared__ float As[16][36];   // stride 144B (16B-aligned)
    __shared__ float Bs[16][64];

    const int i0 = blockIdx.x * 32;
    const int j0 = blockIdx.y * 64;
    const int tid = threadIdx.x;

    {
        float uu = 0.f, cc = 0.f;
#pragma unroll
        for (int b = 0; b < KCH; b++) {
            uu += g_upart[b * HDIM + tid];
            cc += g_cpart[b * HDIM + tid];
        }
        us[tid] = uu;
        cs[tid] = cc + b1[tid];
    }
    if (tid < 32)
        xs[tid] = (float)(i0 + tid) * (1.0f / (float)GTAB);
    __syncthreads();

    const int tx = tid & 31;       // 32 col groups of 2
    const int ty = tid >> 5;       // 8 row groups of 4

    float acc[4][2];
#pragma unroll
    for (int m = 0; m < 4; m++) { acc[m][0] = 0.f; acc[m][1] = 0.f; }

    for (int k0 = 0; k0 < HDIM; k0 += 16) {
#pragma unroll
        for (int s = 0; s < 2; s++) {           // As: 512 elems
            int e = tid + s * 256;
            int kk = e >> 5, ii = e & 31;
            As[kk][ii] = fmaxf(fmaf(xs[ii], us[k0 + kk], cs[k0 + kk]), 0.f);
        }
#pragma unroll
        for (int s = 0; s < 4; s++) {           // Bs: 1024 elems
            int e = tid + s * 256;
            int kk = e >> 6, jj = e & 63;
            Bs[kk][jj] = w2[(k0 + kk) * HDIM + j0 + jj];
        }
        __syncthreads();
#pragma unroll
        for (int kk = 0; kk < 16; kk++) {
            float4 a4 = *reinterpret_cast<const float4*>(&As[kk][ty * 4]);
            float2 bv = *reinterpret_cast<const float2*>(&Bs[kk][tx * 2]);
            float a[4] = {a4.x, a4.y, a4.z, a4.w};
#pragma unroll
            for (int m = 0; m < 4; m++) {
                acc[m][0] = fmaf(a[m], bv.x, acc[m][0]);
                acc[m][1] = fmaf(a[m], bv.y, acc[m][1]);
            }
        }
        __syncthreads();
    }

    float bb0 = b2[j0 + tx * 2];
    float bb1 = b2[j0 + tx * 2 + 1];
#pragma unroll
    for (int m = 0; m < 4; m++) {
        int row = i0 + ty * 4 + m;
        if (row < nrows) {
            float2 v;
            v.x = fmaxf(acc[m][0] + bb0, 0.f);
            v.y = fmaxf(acc[m][1] + bb1, 0.f);
            *reinterpret_cast<float2*>(&g_H2[row * HDIM + j0 + tx * 2]) = v;
        }
    }
}

// ============================================================================
// kT2: A table directly:  A = (H2 @ w3 + b3) @ B^T.
//      Basis arrives as an 8KB kernel parameter (no memcpy graph node).
// ============================================================================
__global__ void __launch_bounds__(256) kT2_atab(
    const BParam Bp,
    const float* __restrict__ w3, const float* __restrict__ b3, int nrows)
{
    __shared__ float H2s[256][33];   // [k][i], 33.8 KB
    __shared__ float Ts[32][33];     // [d][i] (+b3 folded)
    __shared__ float Bs[DTH][64];    // basis

    const int i0 = blockIdx.x * 32;
    const int tid = threadIdx.x;

#pragma unroll
    for (int s = 0; s < 8; s++) {
        int e = tid + s * 256;           // 0..2047 float4 units
        int i = e >> 6, kq = e & 63;
        float4 v = *reinterpret_cast<const float4*>(&g_H2[(i0 + i) * HDIM + kq * 4]);
        H2s[kq * 4 + 0][i] = v.x;
        H2s[kq * 4 + 1][i] = v.y;
        H2s[kq * 4 + 2][i] = v.z;
        H2s[kq * 4 + 3][i] = v.w;
    }
    for (int e = tid; e < DTH * 64; e += 256)
        Bs[e >> 6][e & 63] = Bp.B[e];
    __syncthreads();

    // T = H2 @ w3  (+ b3)
    {
        const int i = tid & 31;
        const int dbase = (tid >> 5) * 4;    // 0,4,...,28
        float acc[4] = {0.f, 0.f, 0.f, 0.f};
#pragma unroll 4
        for (int k = 0; k < HDIM; k++) {
            float h = H2s[k][i];
#pragma unroll
            for (int q = 0; q < 4; q++) {
                int d = dbase + q;
                if (d < DTH)
                    acc[q] = fmaf(h, __ldg(&w3[k * DTH + d]), acc[q]);
            }
        }
#pragma unroll
        for (int q = 0; q < 4; q++) {
            int d = dbase + q;
            if (d < DTH) Ts[d][i] = acc[q] + b3[d];
        }
    }
    __syncthreads();

    // A = T @ B^T
    {
        const int j = tid & 63;
        const int ig = tid >> 6;             // 0..3
        float acc8[8];
#pragma unroll
        for (int m = 0; m < 8; m++) acc8[m] = 0.f;
#pragma unroll
        for (int d = 0; d < DTH; d++) {
            float bv = Bs[d][j];
#pragma unroll
            for (int m = 0; m < 8; m++)
                acc8[m] = fmaf(Ts[d][ig + m * 4], bv, acc8[m]);
        }
#pragma unroll
        for (int m = 0; m < 8; m++) {
            int row = i0 + ig + m * 4;
            if (row < nrows)
                g_Atab[row * 64 + j] = acc8[m];
        }
    }
}

// ============================================================================
// k3: CPAB integration, 1 point/thread (best-measured variant; prefetch and
//     2-pt pairing both tested neutral/negative — k3 is issue-bound).
//     Clamps on c and r removed: xc,x1 in [1e-7, 1-1e-7] guarantees
//     (int)(xc*32) in [0,31] and (int)(x1*1024) in [0,1023].
//     Exact fixpoint early-exit; precise '/' only for e=b/a.
// ============================================================================
__global__ void __launch_bounds__(256) k3_integrate(const float* __restrict__ x,
                                                    float* __restrict__ out, int n)
{
    const int ip = blockIdx.x * 256 + threadIdx.x;
    if (ip >= n) return;

    float2 xv = *reinterpret_cast<const float2*>(&x[2 * ip]);
    float x1 = fminf(fmaxf(xv.y, EPSF), 1.0f - EPSF);
    float f = x1 * (float)GTAB;
    int r = (int)f;                                  // in [0, GTAB-1] by range
    float fr = f - (float)r;
    const float2* row0 = reinterpret_cast<const float2*>(&g_Atab[r * 64]);
    const float2* row1 = reinterpret_cast<const float2*>(&g_Atab[(r + 1) * 64]);

    float xc = fminf(fmaxf(xv.x, EPSF), 1.0f - EPSF);
    float t = 1.0f;
    float S = 0.0f;
    const float inv = 1.0f / (float)NCELL;
    const float INF = __int_as_float(0x7f800000);

#pragma unroll 1
    for (int it = 0; it < NCELL + 2; it++) {
        int c = (int)(xc * (float)NCELL);            // in [0, 31] by range
        float2 p0 = __ldg(&row0[c]);
        float2 p1 = __ldg(&row1[c]);
        float a = fmaf(fr, p1.x - p0.x, p0.x);
        float b = fmaf(fr, p1.y - p0.y, p0.y);
        float v = a * xc + b;
        float xbnd = ((v >= 0.f) ? (float)(c + 1) : (float)c) * inv;
        bool  small_a = fabsf(a) < TINYF;
        float safe_a = small_a ? 1.0f : a;
        float e = b / safe_a;                       // precise: drives drift matching
        float denom = xc + e;
        float safe_denom = (fabsf(denom) < TINYF) ? ((denom >= 0.f) ? TINYF : -TINYF) : denom;
        float ratio = __fdividef(xbnd + e, safe_denom);
        float thit_exp = __fdividef(__logf(fmaxf(ratio, TINYF)), safe_a);
        float safe_b = (fabsf(b) < TINYF) ? TINYF : b;
        float thit_lin = __fdividef(xbnd - xc, safe_b);
        float thit = small_a ? thit_lin : ((ratio > TINYF) ? thit_exp : INF);
        thit = (thit <= 0.f) ? INF : thit;
        float dt = fminf(thit, t);
        bool cross = (thit <= t);
        float x_exp = (xc + e) * __expf(a * dt) - e;
        float x_lin = xc + b * dt;
        float xn = small_a ? x_lin : x_exp;
        float nudge = (v >= 0.f) ? 1e-7f : -1e-7f;
        xn = cross ? (xbnd + nudge) : xn;
        xn = fminf(fmaxf(xn, EPSF), 1.0f - EPSF);
        S += a * dt;
        t = t - dt;
        bool done = (dt == 0.0f) && (xn == xc);     // exact fixpoint
        xc = xn;
        if (__all_sync(0xffffffffu, done)) break;
    }

    float2 z; z.x = xc; z.y = x1;
    *reinterpret_cast<float2*>(&out[2 * ip]) = z;
    float2 g; g.x = S; g.y = 0.0f;
    *reinterpret_cast<float2*>(&out[2 * n + 2 * ip]) = g;
}

// ============================================================================
static BParam s_Bp;               // persists across graph replays

extern "C" void kernel_launch(void* const* d_in, const int* in_sizes, int n_in,
                              void* d_out, int out_size)
{
    const float* x  = (const float*)d_in[0];
    const float* w0 = (const float*)d_in[1];
    const float* b0 = (const float*)d_in[2];
    const float* w1 = (const float*)d_in[3];
    const float* b1 = (const float*)d_in[4];
    const float* w2 = (const float*)d_in[5];
    const float* b2 = (const float*)d_in[6];
    const float* w3 = (const float*)d_in[7];
    const float* b3 = (const float*)d_in[8];
    float* out = (float*)d_out;

    int n = in_sizes[0] / 2;
    const int nrows = GTAB + 1;

    compute_basis_host(s_Bp.B);     // input-independent, deterministic

    dim3 g0(KCH, 2);
    k0u_part<<<g0, 128>>>(w0, b0, w1);

    dim3 g1((nrows + 31) / 32, 4);
    kT1_h2tab<<<g1, 256>>>(b1, w2, b2, nrows);

    kT2_atab<<<(nrows + 31) / 32, 256>>>(s_Bp, w3, b3, nrows);

    k3_integrate<<<(n + 255) / 256, 256>>>(x, out, n);
}